// round 2
// baseline (speedup 1.0000x reference)
#include <cuda_runtime.h>

// Problem constants
#define MTOT 16384      // 2 streams * B(4) * L(2048)
#define HALF_M 8192
#define DIM 512
#define PF 2048
#define NB 4
#define NH 8
#define DH 64
#define LN_EPS 1e-5f

// ---------------- scratch (static device globals; no allocation) -------------
__device__ float g_X   [MTOT * DIM];   // stacked input [question; query]
__device__ float g_Q   [MTOT * DIM];
__device__ float g_K   [MTOT * DIM];
__device__ float g_V   [MTOT * DIM];
__device__ float g_attn[MTOT * DIM];
__device__ float g_proj[MTOT * DIM];
__device__ float g_x1  [MTOT * DIM];
__device__ float g_h1  [MTOT * PF];    // FF intermediate (134 MB)
__device__ float g_ff  [MTOT * DIM];
__device__ float g_S   [NB * NH * DH * DH];  // shared linear-attention state

// ---------------- pack: concat question/query into one batch ----------------
__global__ void pack_kernel(const float* __restrict__ a, const float* __restrict__ b) {
    int i = blockIdx.x * blockDim.x + threadIdx.x;
    const int n4 = HALF_M * DIM / 4;   // 1,048,576 float4s per stream
    float4* X = reinterpret_cast<float4*>(g_X);
    if (i < n4) {
        X[i]      = reinterpret_cast<const float4*>(a)[i];
        X[i + n4] = reinterpret_cast<const float4*>(b)[i];
    }
}

// ---------------- SGEMM: C[M,N] = A[M,K] * W[N,K]^T + bias, opt ReLU ---------
// 128x128 block tile, BK=8, 256 threads, 8x8 per thread.
__global__ void __launch_bounds__(256, 2)
sgemm_kernel(const float* __restrict__ A, const float* __restrict__ W,
             const float* __restrict__ bias, float* __restrict__ C,
             int K, int N, int relu)
{
    __shared__ float As[8][132];
    __shared__ float Bs[8][132];

    const int tid = threadIdx.x;
    const int bm = blockIdx.y, bn = blockIdx.x;

    const float* Ab = A + (size_t)bm * 128 * K;
    const float* Wb = W + (size_t)bn * 128 * K;

    const int ldRow = tid >> 1;          // 0..127
    const int ldCol = (tid & 1) * 4;     // 0 or 4
    const int tx = tid & 15;             // 0..15 -> n
    const int ty = tid >> 4;             // 0..15 -> m

    float acc[8][8];
#pragma unroll
    for (int i = 0; i < 8; i++)
#pragma unroll
        for (int j = 0; j < 8; j++) acc[i][j] = 0.f;

    for (int kt = 0; kt < K; kt += 8) {
        float4 av = *reinterpret_cast<const float4*>(Ab + (size_t)ldRow * K + kt + ldCol);
        float4 wv = *reinterpret_cast<const float4*>(Wb + (size_t)ldRow * K + kt + ldCol);
        As[ldCol + 0][ldRow] = av.x; As[ldCol + 1][ldRow] = av.y;
        As[ldCol + 2][ldRow] = av.z; As[ldCol + 3][ldRow] = av.w;
        Bs[ldCol + 0][ldRow] = wv.x; Bs[ldCol + 1][ldRow] = wv.y;
        Bs[ldCol + 2][ldRow] = wv.z; Bs[ldCol + 3][ldRow] = wv.w;
        __syncthreads();

#pragma unroll
        for (int k = 0; k < 8; k++) {
            float a[8], b[8];
            *reinterpret_cast<float4*>(&a[0]) = *reinterpret_cast<const float4*>(&As[k][ty * 8]);
            *reinterpret_cast<float4*>(&a[4]) = *reinterpret_cast<const float4*>(&As[k][ty * 8 + 4]);
            *reinterpret_cast<float4*>(&b[0]) = *reinterpret_cast<const float4*>(&Bs[k][tx * 8]);
            *reinterpret_cast<float4*>(&b[4]) = *reinterpret_cast<const float4*>(&Bs[k][tx * 8 + 4]);
#pragma unroll
            for (int i = 0; i < 8; i++)
#pragma unroll
                for (int j = 0; j < 8; j++)
                    acc[i][j] += a[i] * b[j];
        }
        __syncthreads();
    }

#pragma unroll
    for (int i = 0; i < 8; i++) {
        int row = bm * 128 + ty * 8 + i;
#pragma unroll
        for (int j = 0; j < 8; j += 4) {
            int col = bn * 128 + tx * 8 + j;
            float4 bv = *reinterpret_cast<const float4*>(bias + col);
            float4 o;
            o.x = acc[i][j + 0] + bv.x;
            o.y = acc[i][j + 1] + bv.y;
            o.z = acc[i][j + 2] + bv.z;
            o.w = acc[i][j + 3] + bv.w;
            if (relu) {
                o.x = fmaxf(o.x, 0.f); o.y = fmaxf(o.y, 0.f);
                o.z = fmaxf(o.z, 0.f); o.w = fmaxf(o.w, 0.f);
            }
            *reinterpret_cast<float4*>(C + (size_t)row * N + col) = o;
        }
    }
}

// ---------------- S state: S[b,h] = K1^T V1 + K2^T V2 (shared by streams) ----
__global__ void __launch_bounds__(256)
s_kernel()
{
    const int b = blockIdx.x >> 3;
    const int h = blockIdx.x & 7;
    __shared__ float Ks[32][64];
    __shared__ float Vs[32][64];

    const int tid = threadIdx.x;
    const int te = tid & 15;   // e-quad
    const int td = tid >> 4;   // d-quad

    float acc[4][4];
#pragma unroll
    for (int i = 0; i < 4; i++)
#pragma unroll
        for (int j = 0; j < 4; j++) acc[i][j] = 0.f;

    for (int s = 0; s < 2; s++) {
        const int rb = (s * 4 + b) * 2048;
        for (int l0 = 0; l0 < 2048; l0 += 32) {
#pragma unroll
            for (int i = 0; i < 2; i++) {
                int idx = tid + i * 256;          // 0..511 float4 slots
                int l = idx >> 4;
                int ec = (idx & 15) * 4;
                size_t goff = (size_t)(rb + l0 + l) * DIM + h * DH + ec;
                *reinterpret_cast<float4*>(&Ks[l][ec]) = *reinterpret_cast<const float4*>(&g_K[goff]);
                *reinterpret_cast<float4*>(&Vs[l][ec]) = *reinterpret_cast<const float4*>(&g_V[goff]);
            }
            __syncthreads();
#pragma unroll 8
            for (int l = 0; l < 32; l++) {
                float kr[4], vr[4];
                *reinterpret_cast<float4*>(kr) = *reinterpret_cast<const float4*>(&Ks[l][te * 4]);
                *reinterpret_cast<float4*>(vr) = *reinterpret_cast<const float4*>(&Vs[l][td * 4]);
#pragma unroll
                for (int i = 0; i < 4; i++)
#pragma unroll
                    for (int j = 0; j < 4; j++)
                        acc[i][j] += kr[i] * vr[j];
            }
            __syncthreads();
        }
    }

    float* Sp = &g_S[(b * 8 + h) * DH * DH];
#pragma unroll
    for (int i = 0; i < 4; i++) {
        int e = te * 4 + i;
        float4 o = make_float4(acc[i][0], acc[i][1], acc[i][2], acc[i][3]);
        *reinterpret_cast<float4*>(&Sp[e * DH + td * 4]) = o;
    }
}

// ---------------- Q @ S -> attn (per-head) ----------------------------------
__global__ void __launch_bounds__(256)
qs_kernel()
{
    const int h = blockIdx.y;
    const int r0 = blockIdx.x * 64;
    const int b = (r0 >> 11) & 3;

    __shared__ float Ss[64][64];
    __shared__ float Qs[64][72];   // padded rows

    const int tid = threadIdx.x;

    const float* Sp = &g_S[(b * 8 + h) * DH * DH];
#pragma unroll
    for (int i = 0; i < 4; i++) {
        int idx = tid + i * 256;   // 1024 float4s = 4096 floats
        reinterpret_cast<float4*>(Ss)[idx] = reinterpret_cast<const float4*>(Sp)[idx];
    }
#pragma unroll
    for (int i = 0; i < 4; i++) {   // FIX: 4 iterations -> all 64 rows of Q tile
        int idx = tid + i * 256;    // 0..1023 float4 slots
        int l = idx >> 4;           // 0..63
        int ec = (idx & 15) * 4;    // 0..60
        *reinterpret_cast<float4*>(&Qs[l][ec]) =
            *reinterpret_cast<const float4*>(&g_Q[(size_t)(r0 + l) * DIM + h * DH + ec]);
    }
    __syncthreads();

    const int rl = tid >> 2;
    const int d0 = (tid & 3) * 16;

    float acc[16];
#pragma unroll
    for (int j = 0; j < 16; j++) acc[j] = 0.f;

#pragma unroll 4
    for (int e = 0; e < 64; e++) {
        float q = Qs[rl][e];
#pragma unroll
        for (int j = 0; j < 16; j += 4) {
            float4 sv = *reinterpret_cast<const float4*>(&Ss[e][d0 + j]);
            acc[j + 0] += q * sv.x;
            acc[j + 1] += q * sv.y;
            acc[j + 2] += q * sv.z;
            acc[j + 3] += q * sv.w;
        }
    }

    size_t base = (size_t)(r0 + rl) * DIM + h * DH + d0;
#pragma unroll
    for (int j = 0; j < 16; j += 4) {
        *reinterpret_cast<float4*>(&g_attn[base + j]) =
            make_float4(acc[j], acc[j + 1], acc[j + 2], acc[j + 3]);
    }
}

// ---------------- fused residual + LayerNorm --------------------------------
// concat==0: out[row*512+c]  ; concat==1: out[rem*1024 + stream*512 + c]
__global__ void __launch_bounds__(128)
ln_kernel(const float* __restrict__ A, const float* __restrict__ R,
          const float* __restrict__ gamma, const float* __restrict__ beta,
          float* __restrict__ out, int concat)
{
    const int row = blockIdx.x;
    const int tid = threadIdx.x;
    const int c = tid * 4;
    const size_t off = (size_t)row * DIM + c;

    float4 a = *reinterpret_cast<const float4*>(A + off);
    float4 r = *reinterpret_cast<const float4*>(R + off);
    float v0 = a.x + r.x, v1 = a.y + r.y, v2 = a.z + r.z, v3 = a.w + r.w;

    float s = v0 + v1 + v2 + v3;
    float q = v0 * v0 + v1 * v1 + v2 * v2 + v3 * v3;
#pragma unroll
    for (int o = 16; o > 0; o >>= 1) {
        s += __shfl_xor_sync(0xffffffffu, s, o);
        q += __shfl_xor_sync(0xffffffffu, q, o);
    }
    __shared__ float ss[4], sq[4];
    if ((tid & 31) == 0) { ss[tid >> 5] = s; sq[tid >> 5] = q; }
    __syncthreads();
    s = ss[0] + ss[1] + ss[2] + ss[3];
    q = sq[0] + sq[1] + sq[2] + sq[3];

    const float mean = s * (1.f / DIM);
    const float var = q * (1.f / DIM) - mean * mean;
    const float rstd = rsqrtf(var + LN_EPS);

    float4 gv = *reinterpret_cast<const float4*>(gamma + c);
    float4 bv = *reinterpret_cast<const float4*>(beta + c);
    float4 o;
    o.x = (v0 - mean) * rstd * gv.x + bv.x;
    o.y = (v1 - mean) * rstd * gv.y + bv.y;
    o.z = (v2 - mean) * rstd * gv.z + bv.z;
    o.w = (v3 - mean) * rstd * gv.w + bv.w;

    if (!concat) {
        *reinterpret_cast<float4*>(out + off) = o;
    } else {
        int sdx = row >> 13;          // 0 = question, 1 = query
        int rem = row & 8191;         // b*2048 + l
        *reinterpret_cast<float4*>(out + (size_t)rem * 1024 + sdx * 512 + c) = o;
    }
}

// ---------------- launch -----------------------------------------------------
extern "C" void kernel_launch(void* const* d_in, const int* in_sizes, int n_in,
                              void* d_out, int out_size)
{
    (void)in_sizes; (void)n_in; (void)out_size;
    const float* question = (const float*)d_in[0];
    const float* query    = (const float*)d_in[1];
    const float* Wq = (const float*)d_in[2];
    const float* bq = (const float*)d_in[3];
    const float* Wk = (const float*)d_in[4];
    const float* bk = (const float*)d_in[5];
    const float* Wv = (const float*)d_in[6];
    const float* bv = (const float*)d_in[7];
    const float* Wo = (const float*)d_in[8];
    const float* bo = (const float*)d_in[9];
    const float* ln_g = (const float*)d_in[10];
    const float* ln_b = (const float*)d_in[11];
    const float* W1 = (const float*)d_in[12];
    const float* b1 = (const float*)d_in[13];
    const float* W2 = (const float*)d_in[14];
    const float* b2 = (const float*)d_in[15];
    float* out = (float*)d_out;

    float *X, *Q, *K, *V, *attn, *proj, *x1, *h1, *ff;
    cudaGetSymbolAddress((void**)&X,    g_X);
    cudaGetSymbolAddress((void**)&Q,    g_Q);
    cudaGetSymbolAddress((void**)&K,    g_K);
    cudaGetSymbolAddress((void**)&V,    g_V);
    cudaGetSymbolAddress((void**)&attn, g_attn);
    cudaGetSymbolAddress((void**)&proj, g_proj);
    cudaGetSymbolAddress((void**)&x1,   g_x1);
    cudaGetSymbolAddress((void**)&h1,   g_h1);
    cudaGetSymbolAddress((void**)&ff,   g_ff);

    // 1. stack streams: X = [question; query]  (16384 x 512)
    pack_kernel<<<(HALF_M * DIM / 4 + 255) / 256, 256>>>(question, query);

    // 2. QKV projections (shared weights, both streams at once)
    dim3 g512(DIM / 128, MTOT / 128);    // (4, 128)
    sgemm_kernel<<<g512, 256>>>(X, Wq, bq, Q, DIM, DIM, 0);
    sgemm_kernel<<<g512, 256>>>(X, Wk, bk, K, DIM, DIM, 0);
    sgemm_kernel<<<g512, 256>>>(X, Wv, bv, V, DIM, DIM, 0);

    // 3. linear-attention state S[b,h] = K1^T V1 + K2^T V2 (shared both ways)
    s_kernel<<<NB * NH, 256>>>();

    // 4. attn = Q @ S
    qs_kernel<<<dim3(MTOT / 64, NH), 256>>>();

    // 5. output projection
    sgemm_kernel<<<g512, 256>>>(attn, Wo, bo, proj, DIM, DIM, 0);

    // 6. LN1: x = LN(input + proj)
    ln_kernel<<<MTOT, 128>>>(X, proj, ln_g, ln_b, x1, 0);

    // 7. FF1 (ReLU fused)
    sgemm_kernel<<<dim3(PF / 128, MTOT / 128), 256>>>(x1, W1, b1, h1, DIM, PF, 1);

    // 8. FF2
    sgemm_kernel<<<dim3(DIM / 128, MTOT / 128), 256>>>(h1, W2, b2, ff, PF, DIM, 0);

    // 9. LN2 + residual + concat directly into output
    ln_kernel<<<MTOT, 128>>>(x1, ff, ln_g, ln_b, out, 1);
}

// round 4
// speedup vs baseline: 2.6208x; 2.6208x over previous
#include <cuda_runtime.h>
#include <cstdint>

// Problem constants
#define MTOT 16384      // 2 streams * B(4) * L(2048)
#define HALF_M 8192
#define DIM 512
#define PF 2048
#define NB 4
#define NH 8
#define DH 64
#define LN_EPS 1e-5f

// ---------------- scratch (static device globals; no allocation) -------------
__device__ float g_X   [MTOT * DIM];
__device__ float g_Q   [MTOT * DIM];
__device__ float g_K   [MTOT * DIM];
__device__ float g_V   [MTOT * DIM];
__device__ float g_attn[MTOT * DIM];
__device__ float g_proj[MTOT * DIM];
__device__ float g_x1  [MTOT * DIM];
__device__ float g_h1  [MTOT * PF];
__device__ float g_ff  [MTOT * DIM];
__device__ float g_S   [NB * NH * DH * DH];

// ---------------- helpers ----------------------------------------------------
__device__ __forceinline__ uint32_t f2tf(float f) {
    uint32_t r;
    asm("cvt.rna.tf32.f32 %0, %1;" : "=r"(r) : "f"(f));
    return r;
}
__device__ __forceinline__ void mma_tf32(float& c0, float& c1, float& c2, float& c3,
                                         uint32_t a0, uint32_t a1, uint32_t a2, uint32_t a3,
                                         uint32_t b0, uint32_t b1)
{
    asm volatile(
        "mma.sync.aligned.m16n8k8.row.col.f32.tf32.tf32.f32 "
        "{%0,%1,%2,%3}, {%4,%5,%6,%7}, {%8,%9}, {%0,%1,%2,%3};"
        : "+f"(c0), "+f"(c1), "+f"(c2), "+f"(c3)
        : "r"(a0), "r"(a1), "r"(a2), "r"(a3), "r"(b0), "r"(b1));
}

// ---------------- pack -------------------------------------------------------
__global__ void pack_kernel(const float* __restrict__ a, const float* __restrict__ b) {
    int i = blockIdx.x * blockDim.x + threadIdx.x;
    const int n4 = HALF_M * DIM / 4;
    float4* X = reinterpret_cast<float4*>(g_X);
    if (i < n4) {
        X[i]      = reinterpret_cast<const float4*>(a)[i];
        X[i + n4] = reinterpret_cast<const float4*>(b)[i];
    }
}

// ============ tf32 mma.sync GEMM: C[M,N] = A[M,K] @ W[N,K]^T + bias ==========
// 128x128 CTA tile, BK=32, 256 threads (8 warps, 2x4), warp tile 64x32.
// SMEM: row-major [128][36] float (pad 4 -> fragment banks 4m+k mod 32, conflict-free)
#define LDPAD 36
#define BUFSZ (128 * LDPAD)   // floats per operand buffer

__global__ void __launch_bounds__(256)
tc_gemm_kernel(const float* __restrict__ A, const float* __restrict__ W,
               const float* __restrict__ bias, float* __restrict__ C,
               int K, int N, int relu)
{
    extern __shared__ float smem[];  // [A0 | W0 | A1 | W1], each BUFSZ floats

    const int tid  = threadIdx.x;
    const int wid  = tid >> 5;
    const int lane = tid & 31;
    const int g    = lane >> 2;      // group id 0..7
    const int tg   = lane & 3;       // thread-in-group 0..3
    const int wm   = wid >> 2;       // 0..1
    const int wn   = wid & 3;        // 0..3
    const int bm = blockIdx.y, bn = blockIdx.x;

    const float* Ag = A + (size_t)bm * 128 * K;
    const float* Wg = W + (size_t)bn * 128 * K;

    // per-thread global-load mapping: 4 x LDG.128 per operand per chunk
    const int ldRow = tid >> 3;           // row advances by 32 per i (idx>>3)
    const int ldSeg = tid & 7;            // 16B segment within the 32-float chunk row

    float acc[4][4][4];
#pragma unroll
    for (int mi = 0; mi < 4; mi++)
#pragma unroll
        for (int ni = 0; ni < 4; ni++)
#pragma unroll
            for (int r = 0; r < 4; r++) acc[mi][ni][r] = 0.f;

    const int NC = K >> 5;

    // ---- load chunk 0 directly
    {
        float* As = smem;
        float* Ws = smem + BUFSZ;
#pragma unroll
        for (int i = 0; i < 4; i++) {
            int row = ldRow + i * 32;
            size_t goff = (size_t)row * K + ldSeg * 4;
            float4 av = __ldg(reinterpret_cast<const float4*>(Ag + goff));
            float4 wv = __ldg(reinterpret_cast<const float4*>(Wg + goff));
            uint32_t* ap = reinterpret_cast<uint32_t*>(&As[row * LDPAD + ldSeg * 4]);
            uint32_t* wp = reinterpret_cast<uint32_t*>(&Ws[row * LDPAD + ldSeg * 4]);
            ap[0] = f2tf(av.x); ap[1] = f2tf(av.y); ap[2] = f2tf(av.z); ap[3] = f2tf(av.w);
            wp[0] = f2tf(wv.x); wp[1] = f2tf(wv.y); wp[2] = f2tf(wv.z); wp[3] = f2tf(wv.w);
        }
    }
    __syncthreads();

    for (int c = 0; c < NC; ++c) {
        const int cur = c & 1;
        const float* As = smem + cur * 2 * BUFSZ;
        const float* Ws = As + BUFSZ;
        const uint32_t* Au = reinterpret_cast<const uint32_t*>(As);
        const uint32_t* Wu = reinterpret_cast<const uint32_t*>(Ws);

        // prefetch chunk c+1 into registers
        float4 pa[4], pw[4];
        const bool more = (c + 1 < NC);
        if (more) {
#pragma unroll
            for (int i = 0; i < 4; i++) {
                int row = ldRow + i * 32;
                size_t goff = (size_t)row * K + (size_t)(c + 1) * 32 + ldSeg * 4;
                pa[i] = __ldg(reinterpret_cast<const float4*>(Ag + goff));
                pw[i] = __ldg(reinterpret_cast<const float4*>(Wg + goff));
            }
        }

        // compute 4 k-slices of 8
#pragma unroll
        for (int ks = 0; ks < 4; ks++) {
            const int k0 = ks * 8 + tg;
            uint32_t a[4][4];
#pragma unroll
            for (int mi = 0; mi < 4; mi++) {
                int m0 = wm * 64 + mi * 16 + g;
                a[mi][0] = Au[m0 * LDPAD + k0];
                a[mi][1] = Au[(m0 + 8) * LDPAD + k0];
                a[mi][2] = Au[m0 * LDPAD + k0 + 4];
                a[mi][3] = Au[(m0 + 8) * LDPAD + k0 + 4];
            }
            uint32_t b[4][2];
#pragma unroll
            for (int ni = 0; ni < 4; ni++) {
                int n0 = wn * 32 + ni * 8 + g;
                b[ni][0] = Wu[n0 * LDPAD + k0];
                b[ni][1] = Wu[n0 * LDPAD + k0 + 4];
            }
#pragma unroll
            for (int mi = 0; mi < 4; mi++)
#pragma unroll
                for (int ni = 0; ni < 4; ni++)
                    mma_tf32(acc[mi][ni][0], acc[mi][ni][1], acc[mi][ni][2], acc[mi][ni][3],
                             a[mi][0], a[mi][1], a[mi][2], a[mi][3],
                             b[ni][0], b[ni][1]);
        }

        // store prefetched chunk to the other buffer
        if (more) {
            float* An = smem + (cur ^ 1) * 2 * BUFSZ;
            float* Wn = An + BUFSZ;
#pragma unroll
            for (int i = 0; i < 4; i++) {
                int row = ldRow + i * 32;
                uint32_t* ap = reinterpret_cast<uint32_t*>(&An[row * LDPAD + ldSeg * 4]);
                uint32_t* wp = reinterpret_cast<uint32_t*>(&Wn[row * LDPAD + ldSeg * 4]);
                ap[0] = f2tf(pa[i].x); ap[1] = f2tf(pa[i].y); ap[2] = f2tf(pa[i].z); ap[3] = f2tf(pa[i].w);
                wp[0] = f2tf(pw[i].x); wp[1] = f2tf(pw[i].y); wp[2] = f2tf(pw[i].z); wp[3] = f2tf(pw[i].w);
            }
            __syncthreads();
        }
    }

    // ---- epilogue: c0/c1 -> (row, col..col+1), c2/c3 -> (row+8, col..col+1)
    const float2* bias2 = reinterpret_cast<const float2*>(bias);
#pragma unroll
    for (int mi = 0; mi < 4; mi++) {
        int r0 = bm * 128 + wm * 64 + mi * 16 + g;
#pragma unroll
        for (int ni = 0; ni < 4; ni++) {
            int col = bn * 128 + wn * 32 + ni * 8 + 2 * tg;
            float2 bv = __ldg(&bias2[col >> 1]);
            float2 o0, o1;
            o0.x = acc[mi][ni][0] + bv.x;
            o0.y = acc[mi][ni][1] + bv.y;
            o1.x = acc[mi][ni][2] + bv.x;
            o1.y = acc[mi][ni][3] + bv.y;
            if (relu) {
                o0.x = fmaxf(o0.x, 0.f); o0.y = fmaxf(o0.y, 0.f);
                o1.x = fmaxf(o1.x, 0.f); o1.y = fmaxf(o1.y, 0.f);
            }
            *reinterpret_cast<float2*>(C + (size_t)r0 * N + col) = o0;
            *reinterpret_cast<float2*>(C + (size_t)(r0 + 8) * N + col) = o1;
        }
    }
}

// ---------------- S state: S[b,h] = K1^T V1 + K2^T V2 ------------------------
__global__ void __launch_bounds__(256)
s_kernel()
{
    const int b = blockIdx.x >> 3;
    const int h = blockIdx.x & 7;
    __shared__ float Ks[32][64];
    __shared__ float Vs[32][64];

    const int tid = threadIdx.x;
    const int te = tid & 15;
    const int td = tid >> 4;

    float acc[4][4];
#pragma unroll
    for (int i = 0; i < 4; i++)
#pragma unroll
        for (int j = 0; j < 4; j++) acc[i][j] = 0.f;

    for (int s = 0; s < 2; s++) {
        const int rb = (s * 4 + b) * 2048;
        for (int l0 = 0; l0 < 2048; l0 += 32) {
#pragma unroll
            for (int i = 0; i < 2; i++) {
                int idx = tid + i * 256;
                int l = idx >> 4;
                int ec = (idx & 15) * 4;
                size_t goff = (size_t)(rb + l0 + l) * DIM + h * DH + ec;
                *reinterpret_cast<float4*>(&Ks[l][ec]) = *reinterpret_cast<const float4*>(&g_K[goff]);
                *reinterpret_cast<float4*>(&Vs[l][ec]) = *reinterpret_cast<const float4*>(&g_V[goff]);
            }
            __syncthreads();
#pragma unroll 8
            for (int l = 0; l < 32; l++) {
                float kr[4], vr[4];
                *reinterpret_cast<float4*>(kr) = *reinterpret_cast<const float4*>(&Ks[l][te * 4]);
                *reinterpret_cast<float4*>(vr) = *reinterpret_cast<const float4*>(&Vs[l][td * 4]);
#pragma unroll
                for (int i = 0; i < 4; i++)
#pragma unroll
                    for (int j = 0; j < 4; j++)
                        acc[i][j] += kr[i] * vr[j];
            }
            __syncthreads();
        }
    }

    float* Sp = &g_S[(b * 8 + h) * DH * DH];
#pragma unroll
    for (int i = 0; i < 4; i++) {
        int e = te * 4 + i;
        *reinterpret_cast<float4*>(&Sp[e * DH + td * 4]) =
            make_float4(acc[i][0], acc[i][1], acc[i][2], acc[i][3]);
    }
}

// ---------------- Q @ S -> attn ----------------------------------------------
__global__ void __launch_bounds__(256)
qs_kernel()
{
    const int h = blockIdx.y;
    const int r0 = blockIdx.x * 64;
    const int b = (r0 >> 11) & 3;

    __shared__ float Ss[64][64];
    __shared__ float Qs[64][72];

    const int tid = threadIdx.x;

    const float* Sp = &g_S[(b * 8 + h) * DH * DH];
#pragma unroll
    for (int i = 0; i < 4; i++) {
        int idx = tid + i * 256;
        reinterpret_cast<float4*>(Ss)[idx] = reinterpret_cast<const float4*>(Sp)[idx];
    }
#pragma unroll
    for (int i = 0; i < 4; i++) {
        int idx = tid + i * 256;
        int l = idx >> 4;
        int ec = (idx & 15) * 4;
        *reinterpret_cast<float4*>(&Qs[l][ec]) =
            *reinterpret_cast<const float4*>(&g_Q[(size_t)(r0 + l) * DIM + h * DH + ec]);
    }
    __syncthreads();

    const int rl = tid >> 2;
    const int d0 = (tid & 3) * 16;

    float acc[16];
#pragma unroll
    for (int j = 0; j < 16; j++) acc[j] = 0.f;

#pragma unroll 4
    for (int e = 0; e < 64; e++) {
        float q = Qs[rl][e];
#pragma unroll
        for (int j = 0; j < 16; j += 4) {
            float4 sv = *reinterpret_cast<const float4*>(&Ss[e][d0 + j]);
            acc[j + 0] += q * sv.x;
            acc[j + 1] += q * sv.y;
            acc[j + 2] += q * sv.z;
            acc[j + 3] += q * sv.w;
        }
    }

    size_t base = (size_t)(r0 + rl) * DIM + h * DH + d0;
#pragma unroll
    for (int j = 0; j < 16; j += 4) {
        *reinterpret_cast<float4*>(&g_attn[base + j]) =
            make_float4(acc[j], acc[j + 1], acc[j + 2], acc[j + 3]);
    }
}

// ---------------- fused residual + LayerNorm ---------------------------------
__global__ void __launch_bounds__(128)
ln_kernel(const float* __restrict__ A, const float* __restrict__ R,
          const float* __restrict__ gamma, const float* __restrict__ beta,
          float* __restrict__ out, int concat)
{
    const int row = blockIdx.x;
    const int tid = threadIdx.x;
    const int c = tid * 4;
    const size_t off = (size_t)row * DIM + c;

    float4 a = *reinterpret_cast<const float4*>(A + off);
    float4 r = *reinterpret_cast<const float4*>(R + off);
    float v0 = a.x + r.x, v1 = a.y + r.y, v2 = a.z + r.z, v3 = a.w + r.w;

    float s = v0 + v1 + v2 + v3;
    float q = v0 * v0 + v1 * v1 + v2 * v2 + v3 * v3;
#pragma unroll
    for (int o = 16; o > 0; o >>= 1) {
        s += __shfl_xor_sync(0xffffffffu, s, o);
        q += __shfl_xor_sync(0xffffffffu, q, o);
    }
    __shared__ float ss[4], sq[4];
    if ((tid & 31) == 0) { ss[tid >> 5] = s; sq[tid >> 5] = q; }
    __syncthreads();
    s = ss[0] + ss[1] + ss[2] + ss[3];
    q = sq[0] + sq[1] + sq[2] + sq[3];

    const float mean = s * (1.f / DIM);
    const float var = q * (1.f / DIM) - mean * mean;
    const float rstd = rsqrtf(var + LN_EPS);

    float4 gv = *reinterpret_cast<const float4*>(gamma + c);
    float4 bv = *reinterpret_cast<const float4*>(beta + c);
    float4 o;
    o.x = (v0 - mean) * rstd * gv.x + bv.x;
    o.y = (v1 - mean) * rstd * gv.y + bv.y;
    o.z = (v2 - mean) * rstd * gv.z + bv.z;
    o.w = (v3 - mean) * rstd * gv.w + bv.w;

    if (!concat) {
        *reinterpret_cast<float4*>(out + off) = o;
    } else {
        int sdx = row >> 13;
        int rem = row & 8191;
        *reinterpret_cast<float4*>(out + (size_t)rem * 1024 + sdx * 512 + c) = o;
    }
}

// ---------------- launch ------------------------------------------------------
extern "C" void kernel_launch(void* const* d_in, const int* in_sizes, int n_in,
                              void* d_out, int out_size)
{
    (void)in_sizes; (void)n_in; (void)out_size;
    const float* question = (const float*)d_in[0];
    const float* query    = (const float*)d_in[1];
    const float* Wq = (const float*)d_in[2];
    const float* bq = (const float*)d_in[3];
    const float* Wk = (const float*)d_in[4];
    const float* bk = (const float*)d_in[5];
    const float* Wv = (const float*)d_in[6];
    const float* bv = (const float*)d_in[7];
    const float* Wo = (const float*)d_in[8];
    const float* bo = (const float*)d_in[9];
    const float* ln_g = (const float*)d_in[10];
    const float* ln_b = (const float*)d_in[11];
    const float* W1 = (const float*)d_in[12];
    const float* b1 = (const float*)d_in[13];
    const float* W2 = (const float*)d_in[14];
    const float* b2 = (const float*)d_in[15];
    float* out = (float*)d_out;

    float *X, *Q, *K, *V, *attn, *proj, *x1, *h1, *ff;
    cudaGetSymbolAddress((void**)&X,    g_X);
    cudaGetSymbolAddress((void**)&Q,    g_Q);
    cudaGetSymbolAddress((void**)&K,    g_K);
    cudaGetSymbolAddress((void**)&V,    g_V);
    cudaGetSymbolAddress((void**)&attn, g_attn);
    cudaGetSymbolAddress((void**)&proj, g_proj);
    cudaGetSymbolAddress((void**)&x1,   g_x1);
    cudaGetSymbolAddress((void**)&h1,   g_h1);
    cudaGetSymbolAddress((void**)&ff,   g_ff);

    const int SMEM_GEMM = 4 * BUFSZ * 4;   // 73728 bytes
    cudaFuncSetAttribute(tc_gemm_kernel, cudaFuncAttributeMaxDynamicSharedMemorySize, SMEM_GEMM);

    // 1. stack streams
    pack_kernel<<<(HALF_M * DIM / 4 + 255) / 256, 256>>>(question, query);

    // 2. QKV projections (tf32 mma.sync)
    dim3 g512(DIM / 128, MTOT / 128);    // (4, 128)
    tc_gemm_kernel<<<g512, 256, SMEM_GEMM>>>(X, Wq, bq, Q, DIM, DIM, 0);
    tc_gemm_kernel<<<g512, 256, SMEM_GEMM>>>(X, Wk, bk, K, DIM, DIM, 0);
    tc_gemm_kernel<<<g512, 256, SMEM_GEMM>>>(X, Wv, bv, V, DIM, DIM, 0);

    // 3. shared linear-attention state
    s_kernel<<<NB * NH, 256>>>();

    // 4. attn = Q @ S
    qs_kernel<<<dim3(MTOT / 64, NH), 256>>>();

    // 5. output projection
    tc_gemm_kernel<<<g512, 256, SMEM_GEMM>>>(attn, Wo, bo, proj, DIM, DIM, 0);

    // 6. LN1
    ln_kernel<<<MTOT, 128>>>(X, proj, ln_g, ln_b, x1, 0);

    // 7. FF1 (ReLU fused)
    tc_gemm_kernel<<<dim3(PF / 128, MTOT / 128), 256, SMEM_GEMM>>>(x1, W1, b1, h1, DIM, PF, 1);

    // 8. FF2
    tc_gemm_kernel<<<dim3(DIM / 128, MTOT / 128), 256, SMEM_GEMM>>>(h1, W2, b2, ff, PF, DIM, 0);

    // 9. LN2 + residual + concat
    ln_kernel<<<MTOT, 128>>>(x1, ff, ln_g, ln_b, out, 1);
}

// round 5
// speedup vs baseline: 2.8703x; 1.0952x over previous
#include <cuda_runtime.h>
#include <cstdint>

// Problem constants
#define MTOT 16384      // 2 streams * B(4) * L(2048)
#define HALF_M 8192
#define DIM 512
#define PF 2048
#define NB 4
#define NH 8
#define DH 64
#define LN_EPS 1e-5f

// ---------------- scratch (static device globals; no allocation) -------------
__device__ float g_X   [MTOT * DIM];
__device__ float g_Q   [MTOT * DIM];
__device__ float g_K   [MTOT * DIM];
__device__ float g_V   [MTOT * DIM];
__device__ float g_attn[MTOT * DIM];
__device__ float g_proj[MTOT * DIM];
__device__ float g_x1  [MTOT * DIM];
__device__ float g_h1  [MTOT * PF];
__device__ float g_ff  [MTOT * DIM];
__device__ float g_S   [NB * NH * DH * DH];

// ---------------- helpers ----------------------------------------------------
__device__ __forceinline__ uint32_t f2tf(float f) {
    uint32_t r;
    asm("cvt.rna.tf32.f32 %0, %1;" : "=r"(r) : "f"(f));
    return r;
}
__device__ __forceinline__ uint32_t smem_u32(const void* p) {
    uint32_t a;
    asm("{ .reg .u64 t; cvta.to.shared.u64 t, %1; cvt.u32.u64 %0, t; }" : "=r"(a) : "l"(p));
    return a;
}
__device__ __forceinline__ void mma_tf32(float& c0, float& c1, float& c2, float& c3,
                                         uint32_t a0, uint32_t a1, uint32_t a2, uint32_t a3,
                                         uint32_t b0, uint32_t b1)
{
    asm volatile(
        "mma.sync.aligned.m16n8k8.row.col.f32.tf32.tf32.f32 "
        "{%0,%1,%2,%3}, {%4,%5,%6,%7}, {%8,%9}, {%0,%1,%2,%3};"
        : "+f"(c0), "+f"(c1), "+f"(c2), "+f"(c3)
        : "r"(a0), "r"(a1), "r"(a2), "r"(a3), "r"(b0), "r"(b1));
}
__device__ __forceinline__ void ldsm4(uint32_t& r0, uint32_t& r1, uint32_t& r2, uint32_t& r3,
                                      uint32_t addr)
{
    asm volatile("ldmatrix.sync.aligned.m8n8.x4.shared.b16 {%0,%1,%2,%3}, [%4];"
                 : "=r"(r0), "=r"(r1), "=r"(r2), "=r"(r3) : "r"(addr));
}

// ---------------- pack -------------------------------------------------------
__global__ void pack_kernel(const float* __restrict__ a, const float* __restrict__ b) {
    int i = blockIdx.x * blockDim.x + threadIdx.x;
    const int n4 = HALF_M * DIM / 4;
    float4* X = reinterpret_cast<float4*>(g_X);
    if (i < n4) {
        X[i]      = reinterpret_cast<const float4*>(a)[i];
        X[i + n4] = reinterpret_cast<const float4*>(b)[i];
    }
}

// ============ tf32 mma.sync GEMM: C[M,N] = A[M,K] @ W[N,K]^T + bias ==========
// 128x128 CTA tile, BK=32, 256 threads (8 warps, 2x4), warp tile 64x32.
// SMEM: row-major [128][36] float; fragments fetched with ldmatrix.x4.
#define LDPAD 36
#define BUFSZ (128 * LDPAD)   // floats per operand buffer

__global__ void __launch_bounds__(256)
tc_gemm_kernel(const float* __restrict__ A, const float* __restrict__ W,
               const float* __restrict__ bias, float* __restrict__ C,
               int K, int N, int relu)
{
    extern __shared__ float smem[];  // [A0 | W0 | A1 | W1], each BUFSZ floats

    const int tid  = threadIdx.x;
    const int wid  = tid >> 5;
    const int lane = tid & 31;
    const int g    = lane >> 2;      // group id 0..7
    const int tg   = lane & 3;       // thread-in-group 0..3
    const int wm   = wid >> 2;       // 0..1
    const int wn   = wid & 3;        // 0..3
    const int bm = blockIdx.y, bn = blockIdx.x;

    const float* Ag = A + (size_t)bm * 128 * K;
    const float* Wg = W + (size_t)bn * 128 * K;

    // global-load mapping: 4 x LDG.128 per operand per chunk
    const int ldRow = tid >> 3;
    const int ldSeg = tid & 7;

    // ldmatrix per-lane addressing
    const int rowA = ((lane >> 3) & 1) * 8 + (lane & 7);  // + m0
    const int colA = (lane >> 4) * 4;                      // k sub-offset
    const int rowB = ((lane >> 4) & 1) * 8 + (lane & 7);  // + n0
    const int colB = ((lane >> 3) & 1) * 4;

    const uint32_t sb = smem_u32(smem);
    // base byte addrs of fragment rows in buffer 0
    uint32_t aAddr0[4], bAddr0[2];
#pragma unroll
    for (int mi = 0; mi < 4; mi++)
        aAddr0[mi] = sb + 4u * ((wm * 64 + mi * 16 + rowA) * LDPAD + colA);
#pragma unroll
    for (int n2 = 0; n2 < 2; n2++)
        bAddr0[n2] = sb + 4u * (BUFSZ + (wn * 32 + n2 * 16 + rowB) * LDPAD + colB);
    const uint32_t bufStride = 4u * 2u * BUFSZ;   // bytes between double buffers

    float acc[4][4][4];
#pragma unroll
    for (int mi = 0; mi < 4; mi++)
#pragma unroll
        for (int ni = 0; ni < 4; ni++)
#pragma unroll
            for (int r = 0; r < 4; r++) acc[mi][ni][r] = 0.f;

    const int NC = K >> 5;

    // ---- load chunk 0 directly
    {
        float* As = smem;
        float* Ws = smem + BUFSZ;
#pragma unroll
        for (int i = 0; i < 4; i++) {
            int row = ldRow + i * 32;
            size_t goff = (size_t)row * K + ldSeg * 4;
            float4 av = __ldg(reinterpret_cast<const float4*>(Ag + goff));
            float4 wv = __ldg(reinterpret_cast<const float4*>(Wg + goff));
            *reinterpret_cast<uint4*>(&As[row * LDPAD + ldSeg * 4]) =
                make_uint4(f2tf(av.x), f2tf(av.y), f2tf(av.z), f2tf(av.w));
            *reinterpret_cast<uint4*>(&Ws[row * LDPAD + ldSeg * 4]) =
                make_uint4(f2tf(wv.x), f2tf(wv.y), f2tf(wv.z), f2tf(wv.w));
        }
    }
    __syncthreads();

    for (int c = 0; c < NC; ++c) {
        const int cur = c & 1;
        const uint32_t bufOff = cur ? bufStride : 0u;

        // prefetch chunk c+1 into registers
        float4 pa[4], pw[4];
        const bool more = (c + 1 < NC);
        if (more) {
#pragma unroll
            for (int i = 0; i < 4; i++) {
                int row = ldRow + i * 32;
                size_t goff = (size_t)row * K + (size_t)(c + 1) * 32 + ldSeg * 4;
                pa[i] = __ldg(reinterpret_cast<const float4*>(Ag + goff));
                pw[i] = __ldg(reinterpret_cast<const float4*>(Wg + goff));
            }
        }

        // compute 4 k-slices of 8, fragments via ldmatrix
#pragma unroll
        for (int ks = 0; ks < 4; ks++) {
            uint32_t a[4][4];
#pragma unroll
            for (int mi = 0; mi < 4; mi++)
                ldsm4(a[mi][0], a[mi][1], a[mi][2], a[mi][3],
                      aAddr0[mi] + bufOff + ks * 32u);
            uint32_t b[2][4];
#pragma unroll
            for (int n2 = 0; n2 < 2; n2++)
                ldsm4(b[n2][0], b[n2][1], b[n2][2], b[n2][3],
                      bAddr0[n2] + bufOff + ks * 32u);
#pragma unroll
            for (int mi = 0; mi < 4; mi++)
#pragma unroll
                for (int ni = 0; ni < 4; ni++) {
                    const uint32_t b0 = (ni & 1) ? b[ni >> 1][2] : b[ni >> 1][0];
                    const uint32_t b1 = (ni & 1) ? b[ni >> 1][3] : b[ni >> 1][1];
                    mma_tf32(acc[mi][ni][0], acc[mi][ni][1], acc[mi][ni][2], acc[mi][ni][3],
                             a[mi][0], a[mi][1], a[mi][2], a[mi][3], b0, b1);
                }
        }

        // store prefetched chunk to the other buffer
        if (more) {
            float* An = smem + (cur ^ 1) * 2 * BUFSZ;
            float* Wn = An + BUFSZ;
#pragma unroll
            for (int i = 0; i < 4; i++) {
                int row = ldRow + i * 32;
                *reinterpret_cast<uint4*>(&An[row * LDPAD + ldSeg * 4]) =
                    make_uint4(f2tf(pa[i].x), f2tf(pa[i].y), f2tf(pa[i].z), f2tf(pa[i].w));
                *reinterpret_cast<uint4*>(&Wn[row * LDPAD + ldSeg * 4]) =
                    make_uint4(f2tf(pw[i].x), f2tf(pw[i].y), f2tf(pw[i].z), f2tf(pw[i].w));
            }
            __syncthreads();
        }
    }

    // ---- epilogue
    const float2* bias2 = reinterpret_cast<const float2*>(bias);
#pragma unroll
    for (int mi = 0; mi < 4; mi++) {
        int r0 = bm * 128 + wm * 64 + mi * 16 + g;
#pragma unroll
        for (int ni = 0; ni < 4; ni++) {
            int col = bn * 128 + wn * 32 + ni * 8 + 2 * tg;
            float2 bv = __ldg(&bias2[col >> 1]);
            float2 o0, o1;
            o0.x = acc[mi][ni][0] + bv.x;
            o0.y = acc[mi][ni][1] + bv.y;
            o1.x = acc[mi][ni][2] + bv.x;
            o1.y = acc[mi][ni][3] + bv.y;
            if (relu) {
                o0.x = fmaxf(o0.x, 0.f); o0.y = fmaxf(o0.y, 0.f);
                o1.x = fmaxf(o1.x, 0.f); o1.y = fmaxf(o1.y, 0.f);
            }
            *reinterpret_cast<float2*>(C + (size_t)r0 * N + col) = o0;
            *reinterpret_cast<float2*>(C + (size_t)(r0 + 8) * N + col) = o1;
        }
    }
}

// ---------------- S state: S[b,h] = K1^T V1 + K2^T V2 ------------------------
__global__ void __launch_bounds__(256)
s_kernel()
{
    const int b = blockIdx.x >> 3;
    const int h = blockIdx.x & 7;
    __shared__ float Ks[32][64];
    __shared__ float Vs[32][64];

    const int tid = threadIdx.x;
    const int te = tid & 15;
    const int td = tid >> 4;

    float acc[4][4];
#pragma unroll
    for (int i = 0; i < 4; i++)
#pragma unroll
        for (int j = 0; j < 4; j++) acc[i][j] = 0.f;

    for (int s = 0; s < 2; s++) {
        const int rb = (s * 4 + b) * 2048;
        for (int l0 = 0; l0 < 2048; l0 += 32) {
#pragma unroll
            for (int i = 0; i < 2; i++) {
                int idx = tid + i * 256;
                int l = idx >> 4;
                int ec = (idx & 15) * 4;
                size_t goff = (size_t)(rb + l0 + l) * DIM + h * DH + ec;
                *reinterpret_cast<float4*>(&Ks[l][ec]) = *reinterpret_cast<const float4*>(&g_K[goff]);
                *reinterpret_cast<float4*>(&Vs[l][ec]) = *reinterpret_cast<const float4*>(&g_V[goff]);
            }
            __syncthreads();
#pragma unroll 8
            for (int l = 0; l < 32; l++) {
                float kr[4], vr[4];
                *reinterpret_cast<float4*>(kr) = *reinterpret_cast<const float4*>(&Ks[l][te * 4]);
                *reinterpret_cast<float4*>(vr) = *reinterpret_cast<const float4*>(&Vs[l][td * 4]);
#pragma unroll
                for (int i = 0; i < 4; i++)
#pragma unroll
                    for (int j = 0; j < 4; j++)
                        acc[i][j] += kr[i] * vr[j];
            }
            __syncthreads();
        }
    }

    float* Sp = &g_S[(b * 8 + h) * DH * DH];
#pragma unroll
    for (int i = 0; i < 4; i++) {
        int e = te * 4 + i;
        *reinterpret_cast<float4*>(&Sp[e * DH + td * 4]) =
            make_float4(acc[i][0], acc[i][1], acc[i][2], acc[i][3]);
    }
}

// ---------------- Q @ S -> attn ----------------------------------------------
__global__ void __launch_bounds__(256)
qs_kernel()
{
    const int h = blockIdx.y;
    const int r0 = blockIdx.x * 64;
    const int b = (r0 >> 11) & 3;

    __shared__ float Ss[64][64];
    __shared__ float Qs[64][72];

    const int tid = threadIdx.x;

    const float* Sp = &g_S[(b * 8 + h) * DH * DH];
#pragma unroll
    for (int i = 0; i < 4; i++) {
        int idx = tid + i * 256;
        reinterpret_cast<float4*>(Ss)[idx] = reinterpret_cast<const float4*>(Sp)[idx];
    }
#pragma unroll
    for (int i = 0; i < 4; i++) {
        int idx = tid + i * 256;
        int l = idx >> 4;
        int ec = (idx & 15) * 4;
        *reinterpret_cast<float4*>(&Qs[l][ec]) =
            *reinterpret_cast<const float4*>(&g_Q[(size_t)(r0 + l) * DIM + h * DH + ec]);
    }
    __syncthreads();

    const int rl = tid >> 2;
    const int d0 = (tid & 3) * 16;

    float acc[16];
#pragma unroll
    for (int j = 0; j < 16; j++) acc[j] = 0.f;

#pragma unroll 4
    for (int e = 0; e < 64; e++) {
        float q = Qs[rl][e];
#pragma unroll
        for (int j = 0; j < 16; j += 4) {
            float4 sv = *reinterpret_cast<const float4*>(&Ss[e][d0 + j]);
            acc[j + 0] += q * sv.x;
            acc[j + 1] += q * sv.y;
            acc[j + 2] += q * sv.z;
            acc[j + 3] += q * sv.w;
        }
    }

    size_t base = (size_t)(r0 + rl) * DIM + h * DH + d0;
#pragma unroll
    for (int j = 0; j < 16; j += 4) {
        *reinterpret_cast<float4*>(&g_attn[base + j]) =
            make_float4(acc[j], acc[j + 1], acc[j + 2], acc[j + 3]);
    }
}

// ---------------- fused residual + LayerNorm ---------------------------------
__global__ void __launch_bounds__(128)
ln_kernel(const float* __restrict__ A, const float* __restrict__ R,
          const float* __restrict__ gamma, const float* __restrict__ beta,
          float* __restrict__ out, int concat)
{
    const int row = blockIdx.x;
    const int tid = threadIdx.x;
    const int c = tid * 4;
    const size_t off = (size_t)row * DIM + c;

    float4 a = *reinterpret_cast<const float4*>(A + off);
    float4 r = *reinterpret_cast<const float4*>(R + off);
    float v0 = a.x + r.x, v1 = a.y + r.y, v2 = a.z + r.z, v3 = a.w + r.w;

    float s = v0 + v1 + v2 + v3;
    float q = v0 * v0 + v1 * v1 + v2 * v2 + v3 * v3;
#pragma unroll
    for (int o = 16; o > 0; o >>= 1) {
        s += __shfl_xor_sync(0xffffffffu, s, o);
        q += __shfl_xor_sync(0xffffffffu, q, o);
    }
    __shared__ float ss[4], sq[4];
    if ((tid & 31) == 0) { ss[tid >> 5] = s; sq[tid >> 5] = q; }
    __syncthreads();
    s = ss[0] + ss[1] + ss[2] + ss[3];
    q = sq[0] + sq[1] + sq[2] + sq[3];

    const float mean = s * (1.f / DIM);
    const float var = q * (1.f / DIM) - mean * mean;
    const float rstd = rsqrtf(var + LN_EPS);

    float4 gv = *reinterpret_cast<const float4*>(gamma + c);
    float4 bv = *reinterpret_cast<const float4*>(beta + c);
    float4 o;
    o.x = (v0 - mean) * rstd * gv.x + bv.x;
    o.y = (v1 - mean) * rstd * gv.y + bv.y;
    o.z = (v2 - mean) * rstd * gv.z + bv.z;
    o.w = (v3 - mean) * rstd * gv.w + bv.w;

    if (!concat) {
        *reinterpret_cast<float4*>(out + off) = o;
    } else {
        int sdx = row >> 13;
        int rem = row & 8191;
        *reinterpret_cast<float4*>(out + (size_t)rem * 1024 + sdx * 512 + c) = o;
    }
}

// ---------------- launch ------------------------------------------------------
extern "C" void kernel_launch(void* const* d_in, const int* in_sizes, int n_in,
                              void* d_out, int out_size)
{
    (void)in_sizes; (void)n_in; (void)out_size;
    const float* question = (const float*)d_in[0];
    const float* query    = (const float*)d_in[1];
    const float* Wq = (const float*)d_in[2];
    const float* bq = (const float*)d_in[3];
    const float* Wk = (const float*)d_in[4];
    const float* bk = (const float*)d_in[5];
    const float* Wv = (const float*)d_in[6];
    const float* bv = (const float*)d_in[7];
    const float* Wo = (const float*)d_in[8];
    const float* bo = (const float*)d_in[9];
    const float* ln_g = (const float*)d_in[10];
    const float* ln_b = (const float*)d_in[11];
    const float* W1 = (const float*)d_in[12];
    const float* b1 = (const float*)d_in[13];
    const float* W2 = (const float*)d_in[14];
    const float* b2 = (const float*)d_in[15];
    float* out = (float*)d_out;

    float *X, *Q, *K, *V, *attn, *proj, *x1, *h1, *ff;
    cudaGetSymbolAddress((void**)&X,    g_X);
    cudaGetSymbolAddress((void**)&Q,    g_Q);
    cudaGetSymbolAddress((void**)&K,    g_K);
    cudaGetSymbolAddress((void**)&V,    g_V);
    cudaGetSymbolAddress((void**)&attn, g_attn);
    cudaGetSymbolAddress((void**)&proj, g_proj);
    cudaGetSymbolAddress((void**)&x1,   g_x1);
    cudaGetSymbolAddress((void**)&h1,   g_h1);
    cudaGetSymbolAddress((void**)&ff,   g_ff);

    const int SMEM_GEMM = 4 * BUFSZ * 4;   // 73728 bytes
    cudaFuncSetAttribute(tc_gemm_kernel, cudaFuncAttributeMaxDynamicSharedMemorySize, SMEM_GEMM);

    // 1. stack streams
    pack_kernel<<<(HALF_M * DIM / 4 + 255) / 256, 256>>>(question, query);

    // 2. QKV projections (tf32 mma.sync + ldmatrix)
    dim3 g512(DIM / 128, MTOT / 128);    // (4, 128)
    tc_gemm_kernel<<<g512, 256, SMEM_GEMM>>>(X, Wq, bq, Q, DIM, DIM, 0);
    tc_gemm_kernel<<<g512, 256, SMEM_GEMM>>>(X, Wk, bk, K, DIM, DIM, 0);
    tc_gemm_kernel<<<g512, 256, SMEM_GEMM>>>(X, Wv, bv, V, DIM, DIM, 0);

    // 3. shared linear-attention state
    s_kernel<<<NB * NH, 256>>>();

    // 4. attn = Q @ S
    qs_kernel<<<dim3(MTOT / 64, NH), 256>>>();

    // 5. output projection
    tc_gemm_kernel<<<g512, 256, SMEM_GEMM>>>(attn, Wo, bo, proj, DIM, DIM, 0);

    // 6. LN1
    ln_kernel<<<MTOT, 128>>>(X, proj, ln_g, ln_b, x1, 0);

    // 7. FF1 (ReLU fused)
    tc_gemm_kernel<<<dim3(PF / 128, MTOT / 128), 256, SMEM_GEMM>>>(x1, W1, b1, h1, DIM, PF, 1);

    // 8. FF2
    tc_gemm_kernel<<<dim3(DIM / 128, MTOT / 128), 256, SMEM_GEMM>>>(h1, W2, b2, ff, PF, DIM, 0);

    // 9. LN2 + residual + concat
    ln_kernel<<<MTOT, 128>>>(x1, ff, ln_g, ln_b, out, 1);
}